// round 15
// baseline (speedup 1.0000x reference)
#include <cuda_runtime.h>
#include <cuda_fp16.h>
#include <cuda_bf16.h>
#include <cstdint>

#define NN 100000
#define EE 1600000
#define FD 128
#define NG 128
#define OD 16

#define SMS 136                         // smem halves per row (272B)
#define SMEM_GEMM (2 * 128 * SMS * 2)   // 69632 B

// Scratch (device globals — no allocs allowed)
__device__ float  g_deg[NN];                 // dinv = rsqrt(indeg+1)
__device__ int    g_cnt_i[NN];               // in-degree counts
__device__ int    g_off[NN + 1];             // CSR row offsets
__device__ int    g_pos[NN];                 // scatter cursors
__device__ int    g_csr_src[EE];             // src ids grouped by dst
__device__ __half g_bufA_h[(long)NN * FD];   // layer-1 gather source (dinv-prescaled)
__device__ __half g_bufA2_h[(long)NN * FD];  // layer-2 gather source (dinv-prescaled)
__device__ __half g_bufB_h[(long)NN * FD];   // layer-1 output, fp16 (GEMM2 input)
__device__ float  g_pool[NG * FD];
__device__ float  g_cnt[NG];

// ---------------- init (counts + pool) ----------------
__global__ void k_init(int n) {
    int i = blockIdx.x * blockDim.x + threadIdx.x;
    if (i < n) g_cnt_i[i] = 0;
    if (i < NG * FD) g_pool[i] = 0.f;
    if (i < NG) g_cnt[i] = 0.f;
}

__global__ void k_count(const int* __restrict__ ei, int e) {
    int stride = gridDim.x * blockDim.x;
    int gid = blockIdx.x * blockDim.x + threadIdx.x;
    const int4* dst4 = (const int4*)(ei + e);
    int e4 = e >> 2;
    for (int i = gid; i < e4; i += stride) {
        int4 d = dst4[i];
        if ((unsigned)d.x < NN) atomicAdd(&g_cnt_i[d.x], 1);
        if ((unsigned)d.y < NN) atomicAdd(&g_cnt_i[d.y], 1);
        if ((unsigned)d.z < NN) atomicAdd(&g_cnt_i[d.z], 1);
        if ((unsigned)d.w < NN) atomicAdd(&g_cnt_i[d.w], 1);
    }
    for (int i = (e4 << 2) + gid; i < e; i += stride) {
        int d = ei[e + i];
        if ((unsigned)d < NN) atomicAdd(&g_cnt_i[d], 1);
    }
}

__global__ __launch_bounds__(1024) void k_scan(int n) {
    __shared__ int part[1024];
    int t = threadIdx.x;
    int chunk = (n + 1023) / 1024;
    int lo = t * chunk, hi = min(lo + chunk, n);
    int s = 0;
    for (int i = lo; i < hi; i++) s += g_cnt_i[i];
    part[t] = s;
    __syncthreads();
    for (int off = 1; off < 1024; off <<= 1) {
        int tmp = (t >= off) ? part[t - off] : 0;
        __syncthreads();
        part[t] += tmp;
        __syncthreads();
    }
    int run = part[t] - s;  // exclusive base
    for (int i = lo; i < hi; i++) {
        int c = g_cnt_i[i];
        g_off[i] = run;
        g_pos[i] = run;
        g_deg[i] = rsqrtf((float)(c + 1));
        run += c;
    }
    if (t == 1023) g_off[n] = part[1023];
}

__global__ void k_scatter(const int* __restrict__ ei, int e) {
    int stride = gridDim.x * blockDim.x;
    int gid = blockIdx.x * blockDim.x + threadIdx.x;
    const int4* src4 = (const int4*)ei;
    const int4* dst4 = (const int4*)(ei + e);
    int e4 = e >> 2;
    for (int i = gid; i < e4; i += stride) {
        int4 s = src4[i];
        int4 d = dst4[i];
        if ((unsigned)s.x < NN && (unsigned)d.x < NN) g_csr_src[atomicAdd(&g_pos[d.x], 1)] = s.x;
        if ((unsigned)s.y < NN && (unsigned)d.y < NN) g_csr_src[atomicAdd(&g_pos[d.y], 1)] = s.y;
        if ((unsigned)s.z < NN && (unsigned)d.z < NN) g_csr_src[atomicAdd(&g_pos[d.z], 1)] = s.z;
        if ((unsigned)s.w < NN && (unsigned)d.w < NN) g_csr_src[atomicAdd(&g_pos[d.w], 1)] = s.w;
    }
    for (int i = (e4 << 2) + gid; i < e; i += stride) {
        int s = ei[i];
        int d = ei[e + i];
        if ((unsigned)s < NN && (unsigned)d < NN)
            g_csr_src[atomicAdd(&g_pos[d], 1)] = s;
    }
}

// ---------------- tensor-core GEMM: dst = dinv[m]*(A @ W), fp16 ------------
// src_sel: 0 = fp32 Ax input, 1 = fp16 g_bufB_h input.
// dst_sel: 0 = g_bufA_h, 1 = g_bufA2_h. row_base: chunk offset.
__device__ __forceinline__ void mma16816(float* c, const uint32_t* a,
                                         uint32_t b0, uint32_t b1) {
    asm volatile(
        "mma.sync.aligned.m16n8k16.row.col.f32.f16.f16.f32 "
        "{%0,%1,%2,%3}, {%4,%5,%6,%7}, {%8,%9}, {%0,%1,%2,%3};"
        : "+f"(c[0]), "+f"(c[1]), "+f"(c[2]), "+f"(c[3])
        : "r"(a[0]), "r"(a[1]), "r"(a[2]), "r"(a[3]), "r"(b0), "r"(b1));
}

__global__ __launch_bounds__(256) void k_gemm_tc(
    const float* __restrict__ Ax, const float* __restrict__ W,
    int M, int src_sel, int dst_sel, int row_base)
{
    extern __shared__ __align__(16) char smem_raw[];
    __half* As = (__half*)smem_raw;            // [128][SMS]
    __half* Ws = As + 128 * SMS;               // [128][SMS]
    const int tid = threadIdx.x;
    const int row0 = row_base + blockIdx.x * 128;

    if (src_sel) {
        // fp16 input: direct 16B copies from g_bufB_h
        const char* Ah = (const char*)g_bufB_h;
#pragma unroll
        for (int i = 0; i < 8; i++) {
            int idx = tid + i * 256;          // 0..2047
            int r = idx >> 4;                 // 0..127
            int c = (idx & 15) * 8;           // halves, 16B units
            int gr = row0 + r;
            uint4 v = make_uint4(0, 0, 0, 0);
            if (gr < M) v = *(const uint4*)(Ah + (long)gr * 256 + c * 2);
            *(uint4*)(As + r * SMS + c) = v;
        }
    } else {
#pragma unroll
        for (int i = 0; i < 16; i++) {
            int idx = tid + i * 256;
            int r = idx >> 5;
            int c4 = (idx & 31) << 2;
            int gr = row0 + r;
            float4 v = make_float4(0.f, 0.f, 0.f, 0.f);
            if (gr < M) v = *(const float4*)(Ax + (long)gr * 128 + c4);
            *(__half2*)(As + r * SMS + c4)     = __floats2half2_rn(v.x, v.y);
            *(__half2*)(As + r * SMS + c4 + 2) = __floats2half2_rn(v.z, v.w);
        }
    }
#pragma unroll
    for (int i = 0; i < 16; i++) {
        int idx = tid + i * 256;
        int r = idx >> 5;
        int c4 = (idx & 31) << 2;
        float4 v = *(const float4*)(W + (long)r * 128 + c4);
        *(__half2*)(Ws + r * SMS + c4)     = __floats2half2_rn(v.x, v.y);
        *(__half2*)(Ws + r * SMS + c4 + 2) = __floats2half2_rn(v.z, v.w);
    }
    __syncthreads();

    const int warp = tid >> 5, lane = tid & 31;
    const int m_base = (warp >> 1) * 32;
    const int n_base = (warp & 1) * 64;

    float acc[2][8][4];
#pragma unroll
    for (int mt = 0; mt < 2; mt++)
#pragma unroll
        for (int nt = 0; nt < 8; nt++)
#pragma unroll
            for (int q = 0; q < 4; q++) acc[mt][nt][q] = 0.f;

    const int lrow = lane & 15;
    const int lcol = (lane >> 4) << 3;

#pragma unroll
    for (int ks = 0; ks < 8; ks++) {
        int k0 = ks * 16;
        uint32_t a[2][4];
#pragma unroll
        for (int mt = 0; mt < 2; mt++) {
            uint32_t addr = (uint32_t)__cvta_generic_to_shared(
                As + (m_base + mt * 16 + lrow) * SMS + k0 + lcol);
            asm volatile("ldmatrix.sync.aligned.m8n8.x4.shared.b16 {%0,%1,%2,%3}, [%4];"
                         : "=r"(a[mt][0]), "=r"(a[mt][1]), "=r"(a[mt][2]), "=r"(a[mt][3])
                         : "r"(addr));
        }
#pragma unroll
        for (int nt = 0; nt < 4; nt++) {
            uint32_t b[4];
            uint32_t addr = (uint32_t)__cvta_generic_to_shared(
                Ws + (k0 + lrow) * SMS + n_base + nt * 16 + lcol);
            asm volatile("ldmatrix.sync.aligned.m8n8.x4.trans.shared.b16 {%0,%1,%2,%3}, [%4];"
                         : "=r"(b[0]), "=r"(b[1]), "=r"(b[2]), "=r"(b[3])
                         : "r"(addr));
#pragma unroll
            for (int mt = 0; mt < 2; mt++) {
                mma16816(acc[mt][nt * 2],     a[mt], b[0], b[1]);
                mma16816(acc[mt][nt * 2 + 1], a[mt], b[2], b[3]);
            }
        }
    }

    // Epilogue: dinv from counts, fp16 stores to selected buffer
    char* dst = (char*)(dst_sel ? g_bufA2_h : g_bufA_h);
    const int qr = lane >> 2;
    const int qc = (lane & 3) * 2;
#pragma unroll
    for (int mt = 0; mt < 2; mt++) {
        int r0 = row0 + m_base + mt * 16 + qr;
        int r1 = r0 + 8;
        float s0 = (r0 < M) ? rsqrtf((float)(g_cnt_i[r0] + 1)) : 0.f;
        float s1 = (r1 < M) ? rsqrtf((float)(g_cnt_i[r1] + 1)) : 0.f;
#pragma unroll
        for (int nt = 0; nt < 8; nt++) {
            int col = n_base + nt * 8 + qc;
            if (r0 < M)
                *(__half2*)(dst + (long)r0 * 256 + col * 2) =
                    __floats2half2_rn(acc[mt][nt][0] * s0, acc[mt][nt][1] * s0);
            if (r1 < M)
                *(__half2*)(dst + (long)r1 * 256 + col * 2) =
                    __floats2half2_rn(acc[mt][nt][2] * s1, acc[mt][nt][3] * s1);
        }
    }
}

// ---------------- aggregation primitives ----------------
__device__ __forceinline__ uint2 ld_raw(const char* buf, int s, int lane) {
    return __ldg((const uint2*)(buf + (long)s * 256) + lane);
}

__device__ __forceinline__ float4 ld_row(const char* buf, int s, int lane) {
    uint2 u = ld_raw(buf, s, lane);
    float2 f0 = __half22float2(*(const __half2*)&u.x);
    float2 f1 = __half22float2(*(const __half2*)&u.y);
    return make_float4(f0.x, f0.y, f1.x, f1.y);
}

__device__ __forceinline__ void facc(float4& a, float4 v) {
    a.x += v.x; a.y += v.y; a.z += v.z; a.w += v.w;
}

__device__ __forceinline__ __half2 uh2(unsigned u) { return *(__half2*)&u; }

// accumulate 4 rows into fp32 acc via depth-2 HADD2 tree
__device__ __forceinline__ void hacc4(float4& acc, uint2 u0, uint2 u1,
                                      uint2 u2, uint2 u3) {
    __half2 lo = __hadd2(__hadd2(uh2(u0.x), uh2(u1.x)), __hadd2(uh2(u2.x), uh2(u3.x)));
    __half2 hi = __hadd2(__hadd2(uh2(u0.y), uh2(u1.y)), __hadd2(uh2(u2.y), uh2(u3.y)));
    float2 f0 = __half22float2(lo);
    float2 f1 = __half22float2(hi);
    acc.x += f0.x; acc.y += f0.y; acc.z += f1.x; acc.w += f1.y;
}

// dual-node gather with HADD2 trees: nodes d0 and d0+1 (if has1)
__device__ __forceinline__ void dual_gather(const char* buf, int d0, bool has1,
                                            int lane, float4& acc0, float4& acc1) {
    int d1 = d0 + 1;
    acc0 = ld_row(buf, d0, lane);
    acc1 = has1 ? ld_row(buf, d1, lane) : make_float4(0.f, 0.f, 0.f, 0.f);
    int j0 = g_off[d0], h0 = g_off[d0 + 1];
    int j1 = h0, h1 = has1 ? g_off[d1 + 1] : h0;
    int a0 = min((j0 + 3) & ~3, h0);
    for (; j0 < a0; j0++) facc(acc0, ld_row(buf, g_csr_src[j0], lane));
    int a1 = min((j1 + 3) & ~3, h1);
    for (; j1 < a1; j1++) facc(acc1, ld_row(buf, g_csr_src[j1], lane));
    while (j0 + 3 < h0 && j1 + 3 < h1) {
        int4 s0 = *(const int4*)(g_csr_src + j0);
        int4 s1 = *(const int4*)(g_csr_src + j1);
        uint2 u0 = ld_raw(buf, s0.x, lane);
        uint2 v0 = ld_raw(buf, s1.x, lane);
        uint2 u1 = ld_raw(buf, s0.y, lane);
        uint2 v1 = ld_raw(buf, s1.y, lane);
        uint2 u2 = ld_raw(buf, s0.z, lane);
        uint2 v2 = ld_raw(buf, s1.z, lane);
        uint2 u3 = ld_raw(buf, s0.w, lane);
        uint2 v3 = ld_raw(buf, s1.w, lane);
        hacc4(acc0, u0, u1, u2, u3);
        hacc4(acc1, v0, v1, v2, v3);
        j0 += 4; j1 += 4;
    }
    for (; j0 + 3 < h0; j0 += 4) {
        int4 sa = *(const int4*)(g_csr_src + j0);
        uint2 u0 = ld_raw(buf, sa.x, lane);
        uint2 u1 = ld_raw(buf, sa.y, lane);
        uint2 u2 = ld_raw(buf, sa.z, lane);
        uint2 u3 = ld_raw(buf, sa.w, lane);
        hacc4(acc0, u0, u1, u2, u3);
    }
    for (; j0 < h0; j0++) facc(acc0, ld_row(buf, g_csr_src[j0], lane));
    for (; j1 + 3 < h1; j1 += 4) {
        int4 sa = *(const int4*)(g_csr_src + j1);
        uint2 u0 = ld_raw(buf, sa.x, lane);
        uint2 u1 = ld_raw(buf, sa.y, lane);
        uint2 u2 = ld_raw(buf, sa.z, lane);
        uint2 u3 = ld_raw(buf, sa.w, lane);
        hacc4(acc1, u0, u1, u2, u3);
    }
    for (; j1 < h1; j1++) facc(acc1, ld_row(buf, g_csr_src[j1], lane));
}

// ---------------- layer-1 aggregate over [d_begin,d_end): bufB_h fp16 ------
__global__ __launch_bounds__(256) void k_aggregate(const float* __restrict__ bias,
                                                   int d_begin, int d_end) {
    int w = (blockIdx.x * blockDim.x + threadIdx.x) >> 5;
    int lane = threadIdx.x & 31;
    int nw = (gridDim.x * blockDim.x) >> 5;
    float4 b = *(const float4*)(bias + lane * 4);
    const char* buf = (const char*)g_bufA_h;
    for (int d0 = d_begin + 2 * w; d0 < d_end; d0 += 2 * nw) {
        bool has1 = (d0 + 1) < d_end;
        float4 acc0, acc1;
        dual_gather(buf, d0, has1, lane, acc0, acc1);
#pragma unroll
        for (int q = 0; q < 2; q++) {
            if (q == 1 && !has1) break;
            int d = d0 + q;
            float4 acc = q ? acc1 : acc0;
            float sc = g_deg[d];
            float ox = fmaxf(fmaf(sc, acc.x, b.x), 0.f);
            float oy = fmaxf(fmaf(sc, acc.y, b.y), 0.f);
            float oz = fmaxf(fmaf(sc, acc.z, b.z), 0.f);
            float ow = fmaxf(fmaf(sc, acc.w, b.w), 0.f);
            __half2 h0 = __floats2half2_rn(ox, oy);
            __half2 h1 = __floats2half2_rn(oz, ow);
            uint2 pk;
            pk.x = *(unsigned*)&h0;
            pk.y = *(unsigned*)&h1;
            *(uint2*)((char*)g_bufB_h + (long)d * 256 + lane * 8) = pk;
        }
    }
}

// ---------------- layer-2 aggregate + mean-pool: dual-chain ----------------
__global__ __launch_bounds__(256) void k_agg_pool(
    const float* __restrict__ bias, const int* __restrict__ batch, int n)
{
    int w = (blockIdx.x * blockDim.x + threadIdx.x) >> 5;
    int lane = threadIdx.x & 31;
    int nw = (gridDim.x * blockDim.x) >> 5;
    int npb = (n + nw - 1) / nw;
    int n0 = w * npb;
    int n1 = min(n0 + npb, n);
    if (n0 >= n1) return;
    float4 b = *(const float4*)(bias + lane * 4);
    const char* buf = (const char*)g_bufA2_h;
    float4 pacc = make_float4(0.f, 0.f, 0.f, 0.f);
    float cnt = 0.f;
    int cg = batch[n0];
    for (int d = n0; d < n1; d += 2) {
        bool has1 = (d + 1) < n1;
        float4 acc0, acc1;
        dual_gather(buf, d, has1, lane, acc0, acc1);
#pragma unroll
        for (int q = 0; q < 2; q++) {
            if (q == 1 && !has1) break;
            int dd = d + q;
            float4 acc = q ? acc1 : acc0;
            int g = batch[dd];
            if (g != cg) {
                if ((unsigned)cg < NG) {
                    float* p = g_pool + cg * FD + lane * 4;
                    atomicAdd(p + 0, pacc.x); atomicAdd(p + 1, pacc.y);
                    atomicAdd(p + 2, pacc.z); atomicAdd(p + 3, pacc.w);
                    if (lane == 0) atomicAdd(&g_cnt[cg], cnt);
                }
                pacc = make_float4(0.f, 0.f, 0.f, 0.f); cnt = 0.f; cg = g;
            }
            float sc = g_deg[dd];
            pacc.x += fmaxf(fmaf(sc, acc.x, b.x), 0.f);
            pacc.y += fmaxf(fmaf(sc, acc.y, b.y), 0.f);
            pacc.z += fmaxf(fmaf(sc, acc.z, b.z), 0.f);
            pacc.w += fmaxf(fmaf(sc, acc.w, b.w), 0.f);
            cnt += 1.f;
        }
    }
    if ((unsigned)cg < NG) {
        float* p = g_pool + cg * FD + lane * 4;
        atomicAdd(p + 0, pacc.x); atomicAdd(p + 1, pacc.y);
        atomicAdd(p + 2, pacc.z); atomicAdd(p + 3, pacc.w);
        if (lane == 0) atomicAdd(&g_cnt[cg], cnt);
    }
}

// ---------------- final linear ----------------
__global__ void k_final(const float* __restrict__ wc, const float* __restrict__ bc,
                        float* __restrict__ out) {
    int g = blockIdx.x;
    int o = threadIdx.x;
    if (o >= OD) return;
    float inv = 1.f / fmaxf(g_cnt[g], 1.f);
    float s = 0.f;
#pragma unroll 8
    for (int f = 0; f < FD; f++)
        s = fmaf(g_pool[g * FD + f], wc[f * OD + o], s);
    out[g * OD + o] = s * inv + bc[o];
}

extern "C" void kernel_launch(void* const* d_in, const int* in_sizes, int n_in,
                              void* d_out, int out_size) {
    const float* x     = (const float*)d_in[0];
    const int*   ei    = (const int*)d_in[1];
    const int*   batch = (const int*)d_in[2];
    const float* w1    = (const float*)d_in[3];
    const float* b1    = (const float*)d_in[4];
    const float* w2    = (const float*)d_in[5];
    const float* b2    = (const float*)d_in[6];
    const float* wc    = (const float*)d_in[7];
    const float* bc    = (const float*)d_in[8];
    float* out = (float*)d_out;

    int n = in_sizes[0] / FD;      // 100000
    int e = in_sizes[1] / 2;       // 1600000
    int gemm_blocks = (n + 127) / 128;
    int mid = (n / 2 + 127) & ~127;          // 128-aligned split point
    if (mid > n) mid = n;
    int blk_a = mid / 128;
    int blk_b = (n - mid + 127) / 128;

    static cudaStream_t s_side = nullptr;
    static cudaEvent_t ev_fork = nullptr, ev_join = nullptr;
    static cudaEvent_t ev_fork2 = nullptr, ev_join2 = nullptr;
    static bool attr_set = false;
    if (!s_side) {
        cudaStreamCreateWithFlags(&s_side, cudaStreamNonBlocking);
        cudaEventCreateWithFlags(&ev_fork, cudaEventDisableTiming);
        cudaEventCreateWithFlags(&ev_join, cudaEventDisableTiming);
        cudaEventCreateWithFlags(&ev_fork2, cudaEventDisableTiming);
        cudaEventCreateWithFlags(&ev_join2, cudaEventDisableTiming);
    }
    if (!attr_set) {
        cudaFuncSetAttribute(k_gemm_tc, cudaFuncAttributeMaxDynamicSharedMemorySize,
                             SMEM_GEMM);
        attr_set = true;
    }

    // (1) init, (2) count on main — GEMM1 epilogue needs only counts
    k_init<<<(n + 255) / 256, 256>>>(n);
    k_count<<<2048, 256>>>(ei, e);

    // fork: (3) scan + (5) scatter on side; (4) gemm1 on main
    cudaEventRecord(ev_fork, 0);
    cudaStreamWaitEvent(s_side, ev_fork, 0);
    k_scan<<<1, 1024, 0, s_side>>>(n);
    k_gemm_tc<<<gemm_blocks, 256, SMEM_GEMM>>>(x, w1, n, 0, 0, 0);
    k_scatter<<<2048, 256, 0, s_side>>>(ei, e);
    cudaEventRecord(ev_join, s_side);
    cudaStreamWaitEvent(0, ev_join, 0);

    // (6) agg1 on [0,mid) — main
    k_aggregate<<<1024, 256>>>(b1, 0, mid);
    cudaEventRecord(ev_fork2, 0);
    cudaStreamWaitEvent(s_side, ev_fork2, 0);
    // (7) agg1 on [mid,n) — side, concurrent with (8) gemm2 rows [0,mid) — main
    k_aggregate<<<1024, 256, 0, s_side>>>(b1, mid, n);
    cudaEventRecord(ev_join2, s_side);
    if (blk_a > 0)
        k_gemm_tc<<<blk_a, 256, SMEM_GEMM>>>(x, w2, n, 1, 1, 0);
    cudaStreamWaitEvent(0, ev_join2, 0);
    // (9) gemm2 rows [mid,n) — main
    if (blk_b > 0)
        k_gemm_tc<<<blk_b, 256, SMEM_GEMM>>>(x, w2, n, 1, 1, mid);

    // (10) layer-2 aggregate + pool, (11) final
    k_agg_pool<<<2048, 256>>>(b2, batch, n);
    k_final<<<NG, 32>>>(wc, bc, out);
}

// round 16
// speedup vs baseline: 1.0419x; 1.0419x over previous
#include <cuda_runtime.h>
#include <cuda_fp16.h>
#include <cuda_bf16.h>
#include <cstdint>

#define NN 100000
#define EE 1600000
#define FD 128
#define NG 128
#define OD 16

#define SMS 136                         // smem halves per row (272B)
#define SMEM_GEMM (2 * 128 * SMS * 2)   // 69632 B

// Scratch (device globals — no allocs allowed)
__device__ float  g_deg[NN];                 // dinv = rsqrt(indeg+1)
__device__ int    g_cnt_i[NN];               // in-degree counts
__device__ int    g_off[NN + 1];             // CSR row offsets
__device__ int    g_pos[NN];                 // scatter cursors
__device__ int    g_csr_src[EE];             // src ids grouped by dst
__device__ __half g_bufA_h[(long)NN * FD];   // gather source (dinv-prescaled GEMM out)
__device__ __half g_bufB_h[(long)NN * FD];   // layer-1 output, fp16 (GEMM2 input)
__device__ float  g_pool[NG * FD];
__device__ float  g_cnt[NG];

// ---------------- init (counts + pool) ----------------
__global__ void k_init(int n) {
    int i = blockIdx.x * blockDim.x + threadIdx.x;
    if (i < n) g_cnt_i[i] = 0;
    if (i < NG * FD) g_pool[i] = 0.f;
    if (i < NG) g_cnt[i] = 0.f;
}

__global__ void k_count(const int* __restrict__ ei, int e) {
    int stride = gridDim.x * blockDim.x;
    int gid = blockIdx.x * blockDim.x + threadIdx.x;
    const int4* dst4 = (const int4*)(ei + e);
    int e4 = e >> 2;
    for (int i = gid; i < e4; i += stride) {
        int4 d = dst4[i];
        if ((unsigned)d.x < NN) atomicAdd(&g_cnt_i[d.x], 1);
        if ((unsigned)d.y < NN) atomicAdd(&g_cnt_i[d.y], 1);
        if ((unsigned)d.z < NN) atomicAdd(&g_cnt_i[d.z], 1);
        if ((unsigned)d.w < NN) atomicAdd(&g_cnt_i[d.w], 1);
    }
    for (int i = (e4 << 2) + gid; i < e; i += stride) {
        int d = ei[e + i];
        if ((unsigned)d < NN) atomicAdd(&g_cnt_i[d], 1);
    }
}

__global__ __launch_bounds__(1024) void k_scan(int n) {
    __shared__ int part[1024];
    int t = threadIdx.x;
    int chunk = (n + 1023) / 1024;
    int lo = t * chunk, hi = min(lo + chunk, n);
    int s = 0;
    for (int i = lo; i < hi; i++) s += g_cnt_i[i];
    part[t] = s;
    __syncthreads();
    for (int off = 1; off < 1024; off <<= 1) {
        int tmp = (t >= off) ? part[t - off] : 0;
        __syncthreads();
        part[t] += tmp;
        __syncthreads();
    }
    int run = part[t] - s;  // exclusive base
    for (int i = lo; i < hi; i++) {
        int c = g_cnt_i[i];
        g_off[i] = run;
        g_pos[i] = run;
        g_deg[i] = rsqrtf((float)(c + 1));
        run += c;
    }
    if (t == 1023) g_off[n] = part[1023];
}

__global__ void k_scatter(const int* __restrict__ ei, int e) {
    int stride = gridDim.x * blockDim.x;
    int gid = blockIdx.x * blockDim.x + threadIdx.x;
    const int4* src4 = (const int4*)ei;
    const int4* dst4 = (const int4*)(ei + e);
    int e4 = e >> 2;
    for (int i = gid; i < e4; i += stride) {
        int4 s = src4[i];
        int4 d = dst4[i];
        if ((unsigned)s.x < NN && (unsigned)d.x < NN) g_csr_src[atomicAdd(&g_pos[d.x], 1)] = s.x;
        if ((unsigned)s.y < NN && (unsigned)d.y < NN) g_csr_src[atomicAdd(&g_pos[d.y], 1)] = s.y;
        if ((unsigned)s.z < NN && (unsigned)d.z < NN) g_csr_src[atomicAdd(&g_pos[d.z], 1)] = s.z;
        if ((unsigned)s.w < NN && (unsigned)d.w < NN) g_csr_src[atomicAdd(&g_pos[d.w], 1)] = s.w;
    }
    for (int i = (e4 << 2) + gid; i < e; i += stride) {
        int s = ei[i];
        int d = ei[e + i];
        if ((unsigned)s < NN && (unsigned)d < NN)
            g_csr_src[atomicAdd(&g_pos[d], 1)] = s;
    }
}

// ---------------- tensor-core GEMM: g_bufA_h = dinv[m]*(A @ W), fp16 -------
// src_sel: 0 = fp32 Ax input, 1 = fp16 g_bufB_h input.
__device__ __forceinline__ void mma16816(float* c, const uint32_t* a,
                                         uint32_t b0, uint32_t b1) {
    asm volatile(
        "mma.sync.aligned.m16n8k16.row.col.f32.f16.f16.f32 "
        "{%0,%1,%2,%3}, {%4,%5,%6,%7}, {%8,%9}, {%0,%1,%2,%3};"
        : "+f"(c[0]), "+f"(c[1]), "+f"(c[2]), "+f"(c[3])
        : "r"(a[0]), "r"(a[1]), "r"(a[2]), "r"(a[3]), "r"(b0), "r"(b1));
}

__global__ __launch_bounds__(256) void k_gemm_tc(
    const float* __restrict__ Ax, const float* __restrict__ W,
    int M, int src_sel)
{
    extern __shared__ __align__(16) char smem_raw[];
    __half* As = (__half*)smem_raw;            // [128][SMS]
    __half* Ws = As + 128 * SMS;               // [128][SMS]
    const int tid = threadIdx.x;
    const int row0 = blockIdx.x * 128;

    if (src_sel) {
        // fp16 input: direct 16B copies from g_bufB_h
        const char* Ah = (const char*)g_bufB_h;
#pragma unroll
        for (int i = 0; i < 8; i++) {
            int idx = tid + i * 256;          // 0..2047
            int r = idx >> 4;                 // 0..127
            int c = (idx & 15) * 8;           // halves
            int gr = row0 + r;
            uint4 v = make_uint4(0, 0, 0, 0);
            if (gr < M) v = *(const uint4*)(Ah + (long)gr * 256 + c * 2);
            *(uint4*)(As + r * SMS + c) = v;
        }
    } else {
#pragma unroll
        for (int i = 0; i < 16; i++) {
            int idx = tid + i * 256;
            int r = idx >> 5;
            int c4 = (idx & 31) << 2;
            int gr = row0 + r;
            float4 v = make_float4(0.f, 0.f, 0.f, 0.f);
            if (gr < M) v = *(const float4*)(Ax + (long)gr * 128 + c4);
            *(__half2*)(As + r * SMS + c4)     = __floats2half2_rn(v.x, v.y);
            *(__half2*)(As + r * SMS + c4 + 2) = __floats2half2_rn(v.z, v.w);
        }
    }
#pragma unroll
    for (int i = 0; i < 16; i++) {
        int idx = tid + i * 256;
        int r = idx >> 5;
        int c4 = (idx & 31) << 2;
        float4 v = *(const float4*)(W + (long)r * 128 + c4);
        *(__half2*)(Ws + r * SMS + c4)     = __floats2half2_rn(v.x, v.y);
        *(__half2*)(Ws + r * SMS + c4 + 2) = __floats2half2_rn(v.z, v.w);
    }
    __syncthreads();

    const int warp = tid >> 5, lane = tid & 31;
    const int m_base = (warp >> 1) * 32;
    const int n_base = (warp & 1) * 64;

    float acc[2][8][4];
#pragma unroll
    for (int mt = 0; mt < 2; mt++)
#pragma unroll
        for (int nt = 0; nt < 8; nt++)
#pragma unroll
            for (int q = 0; q < 4; q++) acc[mt][nt][q] = 0.f;

    const int lrow = lane & 15;
    const int lcol = (lane >> 4) << 3;

#pragma unroll
    for (int ks = 0; ks < 8; ks++) {
        int k0 = ks * 16;
        uint32_t a[2][4];
#pragma unroll
        for (int mt = 0; mt < 2; mt++) {
            uint32_t addr = (uint32_t)__cvta_generic_to_shared(
                As + (m_base + mt * 16 + lrow) * SMS + k0 + lcol);
            asm volatile("ldmatrix.sync.aligned.m8n8.x4.shared.b16 {%0,%1,%2,%3}, [%4];"
                         : "=r"(a[mt][0]), "=r"(a[mt][1]), "=r"(a[mt][2]), "=r"(a[mt][3])
                         : "r"(addr));
        }
#pragma unroll
        for (int nt = 0; nt < 4; nt++) {
            uint32_t b[4];
            uint32_t addr = (uint32_t)__cvta_generic_to_shared(
                Ws + (k0 + lrow) * SMS + n_base + nt * 16 + lcol);
            asm volatile("ldmatrix.sync.aligned.m8n8.x4.trans.shared.b16 {%0,%1,%2,%3}, [%4];"
                         : "=r"(b[0]), "=r"(b[1]), "=r"(b[2]), "=r"(b[3])
                         : "r"(addr));
#pragma unroll
            for (int mt = 0; mt < 2; mt++) {
                mma16816(acc[mt][nt * 2],     a[mt], b[0], b[1]);
                mma16816(acc[mt][nt * 2 + 1], a[mt], b[2], b[3]);
            }
        }
    }

    // Epilogue: dinv from counts, fp16 stores
    const int qr = lane >> 2;
    const int qc = (lane & 3) * 2;
#pragma unroll
    for (int mt = 0; mt < 2; mt++) {
        int r0 = row0 + m_base + mt * 16 + qr;
        int r1 = r0 + 8;
        float s0 = (r0 < M) ? rsqrtf((float)(g_cnt_i[r0] + 1)) : 0.f;
        float s1 = (r1 < M) ? rsqrtf((float)(g_cnt_i[r1] + 1)) : 0.f;
#pragma unroll
        for (int nt = 0; nt < 8; nt++) {
            int col = n_base + nt * 8 + qc;
            if (r0 < M)
                *(__half2*)((char*)g_bufA_h + (long)r0 * 256 + col * 2) =
                    __floats2half2_rn(acc[mt][nt][0] * s0, acc[mt][nt][1] * s0);
            if (r1 < M)
                *(__half2*)((char*)g_bufA_h + (long)r1 * 256 + col * 2) =
                    __floats2half2_rn(acc[mt][nt][2] * s1, acc[mt][nt][3] * s1);
        }
    }
}

// ---------------- aggregation primitives ----------------
__device__ __forceinline__ uint2 ld_raw(int s, int lane) {
    return __ldg((const uint2*)((const char*)g_bufA_h + (long)s * 256) + lane);
}

__device__ __forceinline__ float4 ld_row_h(int s, int lane) {
    uint2 u = ld_raw(s, lane);
    float2 f0 = __half22float2(*(const __half2*)&u.x);
    float2 f1 = __half22float2(*(const __half2*)&u.y);
    return make_float4(f0.x, f0.y, f1.x, f1.y);
}

__device__ __forceinline__ void facc(float4& a, float4 v) {
    a.x += v.x; a.y += v.y; a.z += v.z; a.w += v.w;
}

__device__ __forceinline__ __half2 uh2(unsigned u) { return *(__half2*)&u; }

// accumulate 4 rows into fp32 acc via depth-2 HADD2 tree
__device__ __forceinline__ void hacc4(float4& acc, uint2 u0, uint2 u1,
                                      uint2 u2, uint2 u3) {
    __half2 lo = __hadd2(__hadd2(uh2(u0.x), uh2(u1.x)), __hadd2(uh2(u2.x), uh2(u3.x)));
    __half2 hi = __hadd2(__hadd2(uh2(u0.y), uh2(u1.y)), __hadd2(uh2(u2.y), uh2(u3.y)));
    float2 f0 = __half22float2(lo);
    float2 f1 = __half22float2(hi);
    acc.x += f0.x; acc.y += f0.y; acc.z += f1.x; acc.w += f1.y;
}

// dual-node gather with HADD2 trees: nodes d0 and d0+1 (if has1)
__device__ __forceinline__ void dual_gather(int d0, bool has1, int lane,
                                            float4& acc0, float4& acc1) {
    int d1 = d0 + 1;
    acc0 = ld_row_h(d0, lane);
    acc1 = has1 ? ld_row_h(d1, lane) : make_float4(0.f, 0.f, 0.f, 0.f);
    int j0 = g_off[d0], h0 = g_off[d0 + 1];
    int j1 = h0, h1 = has1 ? g_off[d1 + 1] : h0;
    int a0 = min((j0 + 3) & ~3, h0);
    for (; j0 < a0; j0++) facc(acc0, ld_row_h(g_csr_src[j0], lane));
    int a1 = min((j1 + 3) & ~3, h1);
    for (; j1 < a1; j1++) facc(acc1, ld_row_h(g_csr_src[j1], lane));
    while (j0 + 3 < h0 && j1 + 3 < h1) {
        int4 s0 = *(const int4*)(g_csr_src + j0);
        int4 s1 = *(const int4*)(g_csr_src + j1);
        uint2 u0 = ld_raw(s0.x, lane);
        uint2 v0 = ld_raw(s1.x, lane);
        uint2 u1 = ld_raw(s0.y, lane);
        uint2 v1 = ld_raw(s1.y, lane);
        uint2 u2 = ld_raw(s0.z, lane);
        uint2 v2 = ld_raw(s1.z, lane);
        uint2 u3 = ld_raw(s0.w, lane);
        uint2 v3 = ld_raw(s1.w, lane);
        hacc4(acc0, u0, u1, u2, u3);
        hacc4(acc1, v0, v1, v2, v3);
        j0 += 4; j1 += 4;
    }
    for (; j0 + 3 < h0; j0 += 4) {
        int4 sa = *(const int4*)(g_csr_src + j0);
        uint2 u0 = ld_raw(sa.x, lane);
        uint2 u1 = ld_raw(sa.y, lane);
        uint2 u2 = ld_raw(sa.z, lane);
        uint2 u3 = ld_raw(sa.w, lane);
        hacc4(acc0, u0, u1, u2, u3);
    }
    for (; j0 < h0; j0++) facc(acc0, ld_row_h(g_csr_src[j0], lane));
    for (; j1 + 3 < h1; j1 += 4) {
        int4 sa = *(const int4*)(g_csr_src + j1);
        uint2 u0 = ld_raw(sa.x, lane);
        uint2 u1 = ld_raw(sa.y, lane);
        uint2 u2 = ld_raw(sa.z, lane);
        uint2 u3 = ld_raw(sa.w, lane);
        hacc4(acc1, u0, u1, u2, u3);
    }
    for (; j1 < h1; j1++) facc(acc1, ld_row_h(g_csr_src[j1], lane));
}

// ---------------- layer-1 aggregate: dual-chain, fp16 output ---------------
__global__ __launch_bounds__(256) void k_aggregate(const float* __restrict__ bias, int n) {
    int w = (blockIdx.x * blockDim.x + threadIdx.x) >> 5;
    int lane = threadIdx.x & 31;
    int nw = (gridDim.x * blockDim.x) >> 5;
    float4 b = *(const float4*)(bias + lane * 4);
    for (int d0 = 2 * w; d0 < n; d0 += 2 * nw) {
        bool has1 = (d0 + 1) < n;
        float4 acc0, acc1;
        dual_gather(d0, has1, lane, acc0, acc1);
#pragma unroll
        for (int q = 0; q < 2; q++) {
            if (q == 1 && !has1) break;
            int d = d0 + q;
            float4 acc = q ? acc1 : acc0;
            float sc = g_deg[d];
            float ox = fmaxf(fmaf(sc, acc.x, b.x), 0.f);
            float oy = fmaxf(fmaf(sc, acc.y, b.y), 0.f);
            float oz = fmaxf(fmaf(sc, acc.z, b.z), 0.f);
            float ow = fmaxf(fmaf(sc, acc.w, b.w), 0.f);
            __half2 h0 = __floats2half2_rn(ox, oy);
            __half2 h1 = __floats2half2_rn(oz, ow);
            uint2 pk;
            pk.x = *(unsigned*)&h0;
            pk.y = *(unsigned*)&h1;
            *(uint2*)((char*)g_bufB_h + (long)d * 256 + lane * 8) = pk;
        }
    }
}

// ---------------- layer-2 aggregate + mean-pool: dual-chain ----------------
__global__ __launch_bounds__(256) void k_agg_pool(
    const float* __restrict__ bias, const int* __restrict__ batch, int n)
{
    int w = (blockIdx.x * blockDim.x + threadIdx.x) >> 5;
    int lane = threadIdx.x & 31;
    int nw = (gridDim.x * blockDim.x) >> 5;
    int npb = (n + nw - 1) / nw;
    int n0 = w * npb;
    int n1 = min(n0 + npb, n);
    if (n0 >= n1) return;
    float4 b = *(const float4*)(bias + lane * 4);
    float4 pacc = make_float4(0.f, 0.f, 0.f, 0.f);
    float cnt = 0.f;
    int cg = batch[n0];
    for (int d = n0; d < n1; d += 2) {
        bool has1 = (d + 1) < n1;
        float4 acc0, acc1;
        dual_gather(d, has1, lane, acc0, acc1);
#pragma unroll
        for (int q = 0; q < 2; q++) {
            if (q == 1 && !has1) break;
            int dd = d + q;
            float4 acc = q ? acc1 : acc0;
            int g = batch[dd];
            if (g != cg) {
                if ((unsigned)cg < NG) {
                    float* p = g_pool + cg * FD + lane * 4;
                    atomicAdd(p + 0, pacc.x); atomicAdd(p + 1, pacc.y);
                    atomicAdd(p + 2, pacc.z); atomicAdd(p + 3, pacc.w);
                    if (lane == 0) atomicAdd(&g_cnt[cg], cnt);
                }
                pacc = make_float4(0.f, 0.f, 0.f, 0.f); cnt = 0.f; cg = g;
            }
            float sc = g_deg[dd];
            pacc.x += fmaxf(fmaf(sc, acc.x, b.x), 0.f);
            pacc.y += fmaxf(fmaf(sc, acc.y, b.y), 0.f);
            pacc.z += fmaxf(fmaf(sc, acc.z, b.z), 0.f);
            pacc.w += fmaxf(fmaf(sc, acc.w, b.w), 0.f);
            cnt += 1.f;
        }
    }
    if ((unsigned)cg < NG) {
        float* p = g_pool + cg * FD + lane * 4;
        atomicAdd(p + 0, pacc.x); atomicAdd(p + 1, pacc.y);
        atomicAdd(p + 2, pacc.z); atomicAdd(p + 3, pacc.w);
        if (lane == 0) atomicAdd(&g_cnt[cg], cnt);
    }
}

// ---------------- final linear ----------------
__global__ void k_final(const float* __restrict__ wc, const float* __restrict__ bc,
                        float* __restrict__ out) {
    int g = blockIdx.x;
    int o = threadIdx.x;
    if (o >= OD) return;
    float inv = 1.f / fmaxf(g_cnt[g], 1.f);
    float s = 0.f;
#pragma unroll 8
    for (int f = 0; f < FD; f++)
        s = fmaf(g_pool[g * FD + f], wc[f * OD + o], s);
    out[g * OD + o] = s * inv + bc[o];
}

extern "C" void kernel_launch(void* const* d_in, const int* in_sizes, int n_in,
                              void* d_out, int out_size) {
    const float* x     = (const float*)d_in[0];
    const int*   ei    = (const int*)d_in[1];
    const int*   batch = (const int*)d_in[2];
    const float* w1    = (const float*)d_in[3];
    const float* b1    = (const float*)d_in[4];
    const float* w2    = (const float*)d_in[5];
    const float* b2    = (const float*)d_in[6];
    const float* wc    = (const float*)d_in[7];
    const float* bc    = (const float*)d_in[8];
    float* out = (float*)d_out;

    int n = in_sizes[0] / FD;      // 100000
    int e = in_sizes[1] / 2;       // 1600000
    int gemm_blocks = (n + 127) / 128;

    static cudaStream_t s_side = nullptr;
    static cudaEvent_t ev_fork = nullptr, ev_join = nullptr;
    static bool attr_set = false;
    if (!s_side) {
        cudaStreamCreateWithFlags(&s_side, cudaStreamNonBlocking);
        cudaEventCreateWithFlags(&ev_fork, cudaEventDisableTiming);
        cudaEventCreateWithFlags(&ev_join, cudaEventDisableTiming);
    }
    if (!attr_set) {
        cudaFuncSetAttribute(k_gemm_tc, cudaFuncAttributeMaxDynamicSharedMemorySize,
                             SMEM_GEMM);
        attr_set = true;
    }

    // (1) init, (2) count on main — GEMM1 epilogue needs only counts
    k_init<<<(n + 255) / 256, 256>>>(n);
    k_count<<<2048, 256>>>(ei, e);

    // fork: (3) scan + (5) scatter on side; (4) gemm1 on main
    cudaEventRecord(ev_fork, 0);
    cudaStreamWaitEvent(s_side, ev_fork, 0);
    k_scan<<<1, 1024, 0, s_side>>>(n);
    k_gemm_tc<<<gemm_blocks, 256, SMEM_GEMM>>>(x, w1, n, 0);
    k_scatter<<<2048, 256, 0, s_side>>>(ei, e);
    cudaEventRecord(ev_join, s_side);
    cudaStreamWaitEvent(0, ev_join, 0);

    // (6) layer-1 aggregate (dual-chain, fp16 out)
    k_aggregate<<<2048, 256>>>(b1, n);
    // (7) gemm2 (fp16 in), (8) layer-2 aggregate + pool (dual-chain)
    k_gemm_tc<<<gemm_blocks, 256, SMEM_GEMM>>>(x, w2, n, 1);
    k_agg_pool<<<2048, 256>>>(b2, batch, n);

    // (9) final
    k_final<<<NG, 32>>>(wc, bc, out);
}